// round 13
// baseline (speedup 1.0000x reference)
#include <cuda_runtime.h>

#define NMAX 2000128
#define NKEY (1 << 26)
#define NWRD (NKEY / 32)
#define WPB 8192
#define CPB 8192

__device__ unsigned g_mask[NWRD];       // occupancy bitmask (memset 0)
__device__ int g_pfx[NWRD];             // exclusive rank prefix per word
__device__ int g_merge[NMAX];           // bitfield key per point
__device__ unsigned g_keyA[NMAX];       // encoded tvals binned by voxel
__device__ int g_vcount[NMAX];
__device__ int g_voffset[NMAX];
__device__ int g_cellof[NMAX];          // rank -> bitfield key
__device__ int g_cursor[NMAX];
__device__ int g_bsums[8448];

struct Stats {
    unsigned pcmin_bits[4];
    unsigned hmin_e, hmax_e;
    float hmin, hmax;
    int wwin;
};
__device__ Stats g_st;

__device__ __forceinline__ unsigned fenc(float f) {
    unsigned b = __float_as_uint(f);
    return (b & 0x80000000u) ? ~b : (b | 0x80000000u);
}
__device__ __forceinline__ float fdec(unsigned u) {
    return __uint_as_float((u & 0x80000000u) ? (u ^ 0x80000000u) : ~u);
}

__global__ void k_init() {
    int t = threadIdx.x;
    if (t < 4) g_st.pcmin_bits[t] = 0x7F800000u;
    if (t == 4) { g_st.hmin_e = 0xFFFFFFFFu; g_st.hmax_e = 0u; }
}

__global__ void k_stats(const float4* __restrict__ bxyz, const float4* __restrict__ h4,
                        const float* __restrict__ h, int n) {
    int t = blockIdx.x * blockDim.x + threadIdx.x;
    int base = t * 4;
    float m0 = 3.4e38f, m1 = 3.4e38f, m2 = 3.4e38f, m3 = 3.4e38f;
    unsigned he0 = 0xFFFFFFFFu, he1 = 0u;
    if (base + 3 < n) {
        float4 p0 = __ldg(&bxyz[base]);
        float4 p1 = __ldg(&bxyz[base + 1]);
        float4 p2 = __ldg(&bxyz[base + 2]);
        float4 p3 = __ldg(&bxyz[base + 3]);
        float4 hv = __ldg(&h4[t]);
        m0 = fminf(fminf(p0.x, p1.x), fminf(p2.x, p3.x));
        m1 = fminf(fminf(p0.y, p1.y), fminf(p2.y, p3.y));
        m2 = fminf(fminf(p0.z, p1.z), fminf(p2.z, p3.z));
        m3 = fminf(fminf(p0.w, p1.w), fminf(p2.w, p3.w));
        unsigned e0 = fenc(hv.x), e1 = fenc(hv.y), e2 = fenc(hv.z), e3 = fenc(hv.w);
        he0 = min(min(e0, e1), min(e2, e3));
        he1 = max(max(e0, e1), max(e2, e3));
    } else {
        for (int i = base; i < n; i++) {
            float4 p = __ldg(&bxyz[i]);
            m0 = fminf(m0, p.x); m1 = fminf(m1, p.y);
            m2 = fminf(m2, p.z); m3 = fminf(m3, p.w);
            unsigned e = fenc(__ldg(&h[i]));
            he0 = min(he0, e); he1 = max(he1, e);
        }
    }
    #pragma unroll
    for (int o = 16; o; o >>= 1) {
        m0 = fminf(m0, __shfl_down_sync(~0u, m0, o));
        m1 = fminf(m1, __shfl_down_sync(~0u, m1, o));
        m2 = fminf(m2, __shfl_down_sync(~0u, m2, o));
        m3 = fminf(m3, __shfl_down_sync(~0u, m3, o));
        he0 = min(he0, __shfl_down_sync(~0u, he0, o));
        he1 = max(he1, __shfl_down_sync(~0u, he1, o));
    }
    if ((threadIdx.x & 31) == 0) {
        atomicMin(&g_st.pcmin_bits[0], __float_as_uint(m0));
        atomicMin(&g_st.pcmin_bits[1], __float_as_uint(m1));
        atomicMin(&g_st.pcmin_bits[2], __float_as_uint(m2));
        atomicMin(&g_st.pcmin_bits[3], __float_as_uint(m3));
        atomicMin(&g_st.hmin_e, he0);
        atomicMax(&g_st.hmax_e, he1);
    }
}

__global__ void k_merge(const float4* __restrict__ bxyz, const float* __restrict__ vs,
                        float* __restrict__ out, long long V, int n) {
    float mn0 = __uint_as_float(g_st.pcmin_bits[0]);
    float mn1 = __uint_as_float(g_st.pcmin_bits[1]);
    float mn2 = __uint_as_float(g_st.pcmin_bits[2]);
    float mn3 = __uint_as_float(g_st.pcmin_bits[3]);
    float v0 = __ldg(&vs[0]), v1 = __ldg(&vs[1]), v2 = __ldg(&vs[2]), v3 = __ldg(&vs[3]);
    long long O9 = 52LL * V + n;
    int i = blockIdx.x * blockDim.x + threadIdx.x;
    if (i >= n) return;
    float4 p = __ldg(&bxyz[i]);
    int c0 = (int)floorf(__fdiv_rn(__fsub_rn(p.x, mn0), v0));
    int c1 = (int)floorf(__fdiv_rn(__fsub_rn(p.y, mn1), v1));
    int c2 = (int)floorf(__fdiv_rn(__fsub_rn(p.z, mn2), v2));
    int c3 = (int)floorf(__fdiv_rn(__fsub_rn(p.w, mn3), v3));
    int key = (c0 << 24) | (c1 << 16) | (c2 << 8) | c3;
    g_merge[i] = key;
    atomicOr(&g_mask[key >> 5], 1u << (key & 31));
    *(float4*)&out[O9 + 4LL * i] = make_float4((float)c0, (float)c1, (float)c2, (float)c3);
}

__device__ __forceinline__ int blockScanExcl256(int v, int* shw, int& total) {
    int lane = threadIdx.x & 31, w = threadIdx.x >> 5;
    int x = v;
    #pragma unroll
    for (int o = 1; o < 32; o <<= 1) { int y = __shfl_up_sync(~0u, x, o); if (lane >= o) x += y; }
    if (lane == 31) shw[w] = x;
    __syncthreads();
    if (threadIdx.x < 8) {
        int s = shw[threadIdx.x];
        #pragma unroll
        for (int o = 1; o < 8; o <<= 1) { int y = __shfl_up_sync(0xFFu, s, o); if ((int)threadIdx.x >= o) s += y; }
        shw[threadIdx.x] = s;
    }
    __syncthreads();
    int excl = (w ? shw[w - 1] : 0) + x - v;
    total = shw[7];
    __syncthreads();
    return excl;
}

// per-tile popcount sums; block 0 thread 0 finalizes stats
__global__ void k_bits_partial() {
    __shared__ int shw[8];
    if (blockIdx.x == 0 && threadIdx.x == 0) {
        float mn = fdec(g_st.hmin_e), mx = fdec(g_st.hmax_e);
        g_st.hmin = mn; g_st.hmax = mx;
        int w = 64;
        if (mx > 0.0f) {
            float ratio = (mx - mn) / mx;
            if (ratio < 60.0f) w = (int)ratio + 2;
        }
        g_st.wwin = w;
    }
    int base = blockIdx.x * WPB;
    int s = 0;
    for (int it = 0; it < WPB / 256; it++) {
        int idx = base + it * 256 + threadIdx.x;
        if (idx < NWRD) s += __popc(g_mask[idx]);
    }
    #pragma unroll
    for (int o = 16; o; o >>= 1) s += __shfl_down_sync(~0u, s, o);
    if ((threadIdx.x & 31) == 0) shw[threadIdx.x >> 5] = s;
    __syncthreads();
    if (threadIdx.x == 0) {
        int t = 0;
        for (int k = 0; k < 8; k++) t += shw[k];
        g_bsums[blockIdx.x] = t;
    }
}

__global__ void k_scan_bsums(int nb) {
    __shared__ int sh[32];
    int t = threadIdx.x, lane = t & 31, w = t >> 5;
    int c = (nb + 1023) / 1024;
    int loc[16];
    int s = 0;
    for (int j = 0; j < c; j++) {
        int idx = t * c + j;
        int v = (idx < nb) ? g_bsums[idx] : 0;
        loc[j] = s; s += v;
    }
    int x = s;
    #pragma unroll
    for (int o = 1; o < 32; o <<= 1) { int y = __shfl_up_sync(~0u, x, o); if (lane >= o) x += y; }
    if (lane == 31) sh[w] = x;
    __syncthreads();
    if (t < 32) {
        int v2 = sh[t];
        #pragma unroll
        for (int o = 1; o < 32; o <<= 1) { int y = __shfl_up_sync(~0u, v2, o); if (t >= o) v2 += y; }
        sh[t] = v2;
    }
    __syncthreads();
    int excl = (w ? sh[w - 1] : 0) + x - s;
    for (int j = 0; j < c; j++) {
        int idx = t * c + j;
        if (idx < nb) g_bsums[idx] = excl + loc[j];
    }
}

// coalesced per-word rank prefix (SoA)
__global__ void k_bits_final() {
    __shared__ int shw[8];
    int start = blockIdx.x * WPB;
    int base = g_bsums[blockIdx.x];
    for (int it = 0; it < WPB / 256; it++) {
        int idx = start + it * 256 + threadIdx.x;
        int pc = (idx < NWRD) ? __popc(g_mask[idx]) : 0;
        int tot;
        int excl = blockScanExcl256(pc, shw, tot);
        if (idx < NWRD) g_pfx[idx] = base + excl;
        base += tot;
    }
}

// 4 points/thread: rank via popc, vectorized voxel_index store, count, cellof
__global__ void k_count4(float* __restrict__ out, long long V, int n) {
    int t = blockIdx.x * blockDim.x + threadIdx.x;
    int base = t * 4;
    if (base >= n) return;
    long long O = 52LL * V;
    if (base + 3 < n) {
        int4 keys = *(const int4*)&g_merge[base];
        int k0 = keys.x, k1 = keys.y, k2 = keys.z, k3 = keys.w;
        int r0 = g_pfx[k0 >> 5] + __popc(g_mask[k0 >> 5] & ((1u << (k0 & 31)) - 1u));
        int r1 = g_pfx[k1 >> 5] + __popc(g_mask[k1 >> 5] & ((1u << (k1 & 31)) - 1u));
        int r2 = g_pfx[k2 >> 5] + __popc(g_mask[k2 >> 5] & ((1u << (k2 & 31)) - 1u));
        int r3 = g_pfx[k3 >> 5] + __popc(g_mask[k3 >> 5] & ((1u << (k3 & 31)) - 1u));
        __stcs(&g_cellof[r0], k0);
        __stcs(&g_cellof[r1], k1);
        __stcs(&g_cellof[r2], k2);
        __stcs(&g_cellof[r3], k3);
        *(float4*)&out[O + base] = make_float4((float)r0, (float)r1, (float)r2, (float)r3);
        atomicAdd(&g_vcount[r0], 1);
        atomicAdd(&g_vcount[r1], 1);
        atomicAdd(&g_vcount[r2], 1);
        atomicAdd(&g_vcount[r3], 1);
    } else {
        for (int i = base; i < n; i++) {
            int key = g_merge[i];
            int r = g_pfx[key >> 5] + __popc(g_mask[key >> 5] & ((1u << (key & 31)) - 1u));
            __stcs(&g_cellof[r], key);
            out[O + i] = (float)r;
            atomicAdd(&g_vcount[r], 1);
        }
    }
}

__global__ void k_vcount_partial(int nV) {
    __shared__ int shw[8];
    int base = blockIdx.x * CPB;
    int s = 0;
    for (int it = 0; it < CPB / 256; it++) {
        int idx = base + it * 256 + threadIdx.x;
        if (idx < nV) s += g_vcount[idx];
    }
    #pragma unroll
    for (int o = 16; o; o >>= 1) s += __shfl_down_sync(~0u, s, o);
    if ((threadIdx.x & 31) == 0) shw[threadIdx.x >> 5] = s;
    __syncthreads();
    if (threadIdx.x == 0) {
        int t = 0;
        for (int k = 0; k < 8; k++) t += shw[k];
        g_bsums[blockIdx.x] = t;
    }
}

// voffset scan + fused multi-voxel accumulator zeroing + cursor init
__global__ void k_vcount_final(float* __restrict__ out, long long V, int nV) {
    __shared__ int shw[8];
    int start = blockIdx.x * CPB;
    int base = g_bsums[blockIdx.x];
    for (int it = 0; it < CPB / 256; it++) {
        int idx = start + it * 256 + threadIdx.x;
        int v = (idx < nV) ? g_vcount[idx] : 0;
        int tot;
        int excl = blockScanExcl256(v, shw, tot);
        if (idx < nV) {
            g_voffset[idx] = base + excl;
            if (v > 1) {
                long long r = idx;
                out[15LL * V + r * 4 + 0] = 0.f;
                out[15LL * V + r * 4 + 1] = 0.f;
                out[15LL * V + r * 4 + 2] = 0.f;
                out[15LL * V + r * 4 + 3] = 0.f;
                float* fp = &out[19LL * V + r * 32];
                #pragma unroll
                for (int k = 0; k < 32; k++) fp[k] = 0.f;
                g_cursor[idx] = 0;
            }
        }
        base += tot;
    }
}

// warp = 4 points; 8 lanes x float4 per point. VEC=4 requires V%4==0.
template <int VEC>
__global__ void k_accum2v(const float4* __restrict__ bxyz, const float4* __restrict__ feat4,
                          const float* __restrict__ h, float* __restrict__ out,
                          long long V, int n) {
    int gw = (blockIdx.x * blockDim.x + threadIdx.x) >> 5;
    int lane = threadIdx.x & 31;
    int sub = lane >> 3, comp = lane & 7;
    int i = gw * 4 + sub;
    if (i >= n) return;
    int key = g_merge[i];
    int r = g_pfx[key >> 5] + __popc(g_mask[key >> 5] & ((1u << (key & 31)) - 1u));
    int c = g_vcount[r];
    float4 f = __ldcs(&feat4[(long long)i * 8 + comp]);
    long long fbase = 19LL * V + (long long)r * 32 + comp * 4;
    if (c == 1) {
        if (VEC == 4) {
            __stcs((float4*)&out[fbase], f);
        } else {
            __stcs(&out[fbase + 0], f.x);
            __stcs(&out[fbase + 1], f.y);
            __stcs(&out[fbase + 2], f.z);
            __stcs(&out[fbase + 3], f.w);
        }
    } else {
        atomicAdd(&out[fbase + 0], f.x);
        atomicAdd(&out[fbase + 1], f.y);
        atomicAdd(&out[fbase + 2], f.z);
        atomicAdd(&out[fbase + 3], f.w);
    }
    if (comp == 0) {
        float4 b = __ldg(&bxyz[i]);
        long long bo = 15LL * V + (long long)r * 4;
        if (c == 1) {
            if (VEC == 4) {
                *(float4*)&out[bo] = b;
            } else {
                out[bo + 0] = b.x; out[bo + 1] = b.y;
                out[bo + 2] = b.z; out[bo + 3] = b.w;
            }
        } else {
            atomicAdd(&out[bo + 0], b.x);
            atomicAdd(&out[bo + 1], b.y);
            atomicAdd(&out[bo + 2], b.z);
            atomicAdd(&out[bo + 3], b.w);
        }
    } else if (comp == 1) {
        float tv = __fadd_rn(__fsub_rn(__ldg(&h[i]), g_st.hmin), __fmul_rn((float)r, g_st.hmax));
        int pos = (c == 1) ? 0 : atomicAdd(&g_cursor[r], 1);
        g_keyA[g_voffset[r] + pos] = fenc(tv);
    }
}

// fused: per-voxel scalar outputs + feat divide (multi only) + windowed median
__global__ void k_final(float* __restrict__ out, const float* __restrict__ vs,
                        long long V, int N) {
    long long r = (long long)blockIdx.x * blockDim.x + threadIdx.x;
    if (r >= V) return;
    float vs1 = __ldg(&vs[1]), vs2 = __ldg(&vs[2]), vs3 = __ldg(&vs[3]);
    float mn1 = __uint_as_float(g_st.pcmin_bits[1]);
    float mn2 = __uint_as_float(g_st.pcmin_bits[2]);
    float mn3 = __uint_as_float(g_st.pcmin_bits[3]);
    int c = g_vcount[r];
    float sx = out[15LL * V + r * 4 + 0];
    float sy = out[15LL * V + r * 4 + 1];
    float sz = out[15LL * V + r * 4 + 2];
    float sw = out[15LL * V + r * 4 + 3];
    if (c > 1) {
        float fc = (float)c;
        sx = __fdiv_rn(sx, fc);
        sy = __fdiv_rn(sy, fc);
        sz = __fdiv_rn(sz, fc);
        sw = __fdiv_rn(sw, fc);
        out[15LL * V + r * 4 + 0] = sx;
        out[15LL * V + r * 4 + 1] = sy;
        out[15LL * V + r * 4 + 2] = sz;
        out[15LL * V + r * 4 + 3] = sw;
        float* fp = &out[19LL * V + r * 32];
        #pragma unroll 8
        for (int k = 0; k < 32; k++) fp[k] = __fdiv_rn(fp[k], fc);
    }
    int key = g_cellof[r];
    int c0 = (key >> 24) & 255, c1 = (key >> 16) & 255, c2 = (key >> 8) & 255, c3 = key & 255;
    out[r] = (float)(int)rintf(sx);
    out[V + r * 3 + 0] = sy;
    out[V + r * 3 + 1] = sz;
    out[V + r * 3 + 2] = sw;
    float t1 = __fadd_rn(__fmul_rn((float)c1, vs1), mn1);
    float t2 = __fadd_rn(__fmul_rn((float)c2, vs2), mn2);
    float t3 = __fadd_rn(__fmul_rn((float)c3, vs3), mn3);
    float ctr1 = __fadd_rn(t1, __fdiv_rn(vs1, 2.0f));
    float ctr2 = __fadd_rn(t2, __fdiv_rn(vs2, 2.0f));
    float ctr3 = __fadd_rn(t3, __fdiv_rn(vs3, 2.0f));
    out[4LL * V + r * 3 + 0] = ctr1;
    out[4LL * V + r * 3 + 1] = ctr2;
    out[4LL * V + r * 3 + 2] = ctr3;
    out[7LL * V + r * 4 + 0] = sx;
    out[7LL * V + r * 4 + 1] = ctr1;
    out[7LL * V + r * 4 + 2] = ctr2;
    out[7LL * V + r * 4 + 3] = ctr3;
    out[11LL * V + r * 4 + 0] = (float)c0;
    out[11LL * V + r * 4 + 1] = (float)c1;
    out[11LL * V + r * 4 + 2] = (float)c2;
    out[11LL * V + r * 4 + 3] = (float)c3;

    // median: value at global-sort position voffset[r] + c/2, via windowed
    // selection with iterative min-with-multiplicity (exact vs full sort).
    float mx = g_st.hmax;
    int W = g_st.wwin;
    long long lo = r - W; if (lo < 0) lo = 0;
    long long hi = r + W; if (hi > V - 1) hi = V - 1;
    int s0 = g_voffset[lo];
    int sr = g_voffset[r];
    int s1 = (hi + 1 < V) ? g_voffset[hi + 1] : N;
    unsigned thr = fenc(__fmul_rn((float)r, mx));   // >= 0x80000000, so thr-1 safe
    int kk = c >> 1;
    for (int j = s0; j < sr; j++)
        if (__ldg(&g_keyA[j]) >= thr) kk++;
    unsigned last = thr - 1u;
    int remaining = kk + 1;
    unsigned ans = 0u;
    for (int guard = s1 - s0; guard > 0; guard--) {
        unsigned m = 0xFFFFFFFFu;
        int mult = 0;
        for (int j = s0; j < s1; j++) {
            unsigned k = __ldg(&g_keyA[j]);
            if (k > last) {
                if (k < m) { m = k; mult = 1; }
                else if (k == m) mult++;
            }
        }
        if (mult >= remaining) { ans = m; break; }
        remaining -= mult;
        last = m;
    }
    out[51LL * V + r] = __fsub_rn(fdec(ans), __fmul_rn((float)r, mx));
}

extern "C" void kernel_launch(void* const* d_in, const int* in_sizes, int n_in,
                              void* d_out, int out_size) {
    const float* bxyz = (const float*)d_in[0];
    const float* feat = (const float*)d_in[1];
    const float* hh = (const float*)d_in[2];
    const float* vs = (const float*)d_in[3];
    int N = in_sizes[0] / 4;
    long long V = ((long long)out_size - 5LL * N) / 52LL;
    float* out = (float*)d_out;

    void *p_mask = 0, *p_vcount = 0;
    cudaGetSymbolAddress(&p_mask, g_mask);
    cudaGetSymbolAddress(&p_vcount, g_vcount);

    int NBW = (NWRD + WPB - 1) / WPB;
    int NBV = (int)((V + CPB - 1) / CPB);
    int BPT = (N + 255) / 256;
    int BS4 = ((N + 3) / 4 + 255) / 256;
    long long warps4 = ((long long)N + 3) / 4;
    int BW4 = (int)((warps4 * 32 + 255) / 256);
    int BVT = (int)((V + 255) / 256);

    cudaMemsetAsync(p_mask, 0, sizeof(unsigned) * NWRD);
    cudaMemsetAsync(p_vcount, 0, sizeof(int) * (size_t)V);

    k_init<<<1, 32>>>();
    k_stats<<<BS4, 256>>>((const float4*)bxyz, (const float4*)hh, hh, N);
    k_merge<<<BPT, 256>>>((const float4*)bxyz, vs, out, V, N);
    k_bits_partial<<<NBW, 256>>>();
    k_scan_bsums<<<1, 1024>>>(NBW);
    k_bits_final<<<NBW, 256>>>();
    k_count4<<<BS4, 256>>>(out, V, N);
    k_vcount_partial<<<NBV, 256>>>((int)V);
    k_scan_bsums<<<1, 1024>>>(NBV);
    k_vcount_final<<<NBV, 256>>>(out, V, (int)V);
    if ((V & 3) == 0) {
        k_accum2v<4><<<BW4, 256>>>((const float4*)bxyz, (const float4*)feat, hh, out, V, N);
    } else {
        k_accum2v<1><<<BW4, 256>>>((const float4*)bxyz, (const float4*)feat, hh, out, V, N);
    }
    k_final<<<BVT, 256>>>(out, vs, V, N);
}

// round 14
// speedup vs baseline: 1.0234x; 1.0234x over previous
#include <cuda_runtime.h>

#define NMAX 2000128
#define NKEY (1 << 26)
#define NWRD (NKEY / 32)
#define WPB 8192
#define CPB 8192

__device__ unsigned g_mask[NWRD];       // occupancy bitmask (memset 0)
__device__ int g_pfx[NWRD];             // exclusive rank prefix per word
__device__ int g_merge[NMAX];           // bitfield key per point
__device__ unsigned g_keyA[NMAX];       // encoded tvals binned by voxel
__device__ int g_vcount[NMAX];
__device__ int g_voffset[NMAX];
__device__ int g_cellof[NMAX];          // rank -> bitfield key
__device__ int g_cursor[NMAX];
__device__ int g_bsums[8448];
__device__ int g_multilist[NMAX];
__device__ int g_nmulti;

struct Stats {
    unsigned pcmin_bits[4];
    unsigned hmin_e, hmax_e;
    float hmin, hmax;
    int wwin;
};
__device__ Stats g_st;

__device__ __forceinline__ unsigned fenc(float f) {
    unsigned b = __float_as_uint(f);
    return (b & 0x80000000u) ? ~b : (b | 0x80000000u);
}
__device__ __forceinline__ float fdec(unsigned u) {
    return __uint_as_float((u & 0x80000000u) ? (u ^ 0x80000000u) : ~u);
}

__global__ void k_init() {
    int t = threadIdx.x;
    if (t < 4) g_st.pcmin_bits[t] = 0x7F800000u;
    if (t == 4) { g_st.hmin_e = 0xFFFFFFFFu; g_st.hmax_e = 0u; g_nmulti = 0; }
}

__global__ void k_stats(const float4* __restrict__ bxyz, const float4* __restrict__ h4,
                        const float* __restrict__ h, int n) {
    int t = blockIdx.x * blockDim.x + threadIdx.x;
    int base = t * 4;
    float m0 = 3.4e38f, m1 = 3.4e38f, m2 = 3.4e38f, m3 = 3.4e38f;
    unsigned he0 = 0xFFFFFFFFu, he1 = 0u;
    if (base + 3 < n) {
        float4 p0 = __ldg(&bxyz[base]);
        float4 p1 = __ldg(&bxyz[base + 1]);
        float4 p2 = __ldg(&bxyz[base + 2]);
        float4 p3 = __ldg(&bxyz[base + 3]);
        float4 hv = __ldg(&h4[t]);
        m0 = fminf(fminf(p0.x, p1.x), fminf(p2.x, p3.x));
        m1 = fminf(fminf(p0.y, p1.y), fminf(p2.y, p3.y));
        m2 = fminf(fminf(p0.z, p1.z), fminf(p2.z, p3.z));
        m3 = fminf(fminf(p0.w, p1.w), fminf(p2.w, p3.w));
        unsigned e0 = fenc(hv.x), e1 = fenc(hv.y), e2 = fenc(hv.z), e3 = fenc(hv.w);
        he0 = min(min(e0, e1), min(e2, e3));
        he1 = max(max(e0, e1), max(e2, e3));
    } else {
        for (int i = base; i < n; i++) {
            float4 p = __ldg(&bxyz[i]);
            m0 = fminf(m0, p.x); m1 = fminf(m1, p.y);
            m2 = fminf(m2, p.z); m3 = fminf(m3, p.w);
            unsigned e = fenc(__ldg(&h[i]));
            he0 = min(he0, e); he1 = max(he1, e);
        }
    }
    #pragma unroll
    for (int o = 16; o; o >>= 1) {
        m0 = fminf(m0, __shfl_down_sync(~0u, m0, o));
        m1 = fminf(m1, __shfl_down_sync(~0u, m1, o));
        m2 = fminf(m2, __shfl_down_sync(~0u, m2, o));
        m3 = fminf(m3, __shfl_down_sync(~0u, m3, o));
        he0 = min(he0, __shfl_down_sync(~0u, he0, o));
        he1 = max(he1, __shfl_down_sync(~0u, he1, o));
    }
    if ((threadIdx.x & 31) == 0) {
        atomicMin(&g_st.pcmin_bits[0], __float_as_uint(m0));
        atomicMin(&g_st.pcmin_bits[1], __float_as_uint(m1));
        atomicMin(&g_st.pcmin_bits[2], __float_as_uint(m2));
        atomicMin(&g_st.pcmin_bits[3], __float_as_uint(m3));
        atomicMin(&g_st.hmin_e, he0);
        atomicMax(&g_st.hmax_e, he1);
    }
}

__global__ void k_merge(const float4* __restrict__ bxyz, const float* __restrict__ vs,
                        float* __restrict__ out, long long V, int n) {
    float mn0 = __uint_as_float(g_st.pcmin_bits[0]);
    float mn1 = __uint_as_float(g_st.pcmin_bits[1]);
    float mn2 = __uint_as_float(g_st.pcmin_bits[2]);
    float mn3 = __uint_as_float(g_st.pcmin_bits[3]);
    float v0 = __ldg(&vs[0]), v1 = __ldg(&vs[1]), v2 = __ldg(&vs[2]), v3 = __ldg(&vs[3]);
    long long O9 = 52LL * V + n;
    int i = blockIdx.x * blockDim.x + threadIdx.x;
    if (i >= n) return;
    float4 p = __ldg(&bxyz[i]);
    int c0 = (int)floorf(__fdiv_rn(__fsub_rn(p.x, mn0), v0));
    int c1 = (int)floorf(__fdiv_rn(__fsub_rn(p.y, mn1), v1));
    int c2 = (int)floorf(__fdiv_rn(__fsub_rn(p.z, mn2), v2));
    int c3 = (int)floorf(__fdiv_rn(__fsub_rn(p.w, mn3), v3));
    int key = (c0 << 24) | (c1 << 16) | (c2 << 8) | c3;
    g_merge[i] = key;
    atomicOr(&g_mask[key >> 5], 1u << (key & 31));
    *(float4*)&out[O9 + 4LL * i] = make_float4((float)c0, (float)c1, (float)c2, (float)c3);
}

__device__ __forceinline__ int blockScanExcl256(int v, int* shw, int& total) {
    int lane = threadIdx.x & 31, w = threadIdx.x >> 5;
    int x = v;
    #pragma unroll
    for (int o = 1; o < 32; o <<= 1) { int y = __shfl_up_sync(~0u, x, o); if (lane >= o) x += y; }
    if (lane == 31) shw[w] = x;
    __syncthreads();
    if (threadIdx.x < 8) {
        int s = shw[threadIdx.x];
        #pragma unroll
        for (int o = 1; o < 8; o <<= 1) { int y = __shfl_up_sync(0xFFu, s, o); if ((int)threadIdx.x >= o) s += y; }
        shw[threadIdx.x] = s;
    }
    __syncthreads();
    int excl = (w ? shw[w - 1] : 0) + x - v;
    total = shw[7];
    __syncthreads();
    return excl;
}

// per-tile popcount sums; block 0 thread 0 finalizes stats
__global__ void k_bits_partial() {
    __shared__ int shw[8];
    if (blockIdx.x == 0 && threadIdx.x == 0) {
        float mn = fdec(g_st.hmin_e), mx = fdec(g_st.hmax_e);
        g_st.hmin = mn; g_st.hmax = mx;
        int w = 64;
        if (mx > 0.0f) {
            float ratio = (mx - mn) / mx;
            if (ratio < 60.0f) w = (int)ratio + 2;
        }
        g_st.wwin = w;
    }
    int base = blockIdx.x * WPB;
    int s = 0;
    for (int it = 0; it < WPB / 256; it++) {
        int idx = base + it * 256 + threadIdx.x;
        if (idx < NWRD) s += __popc(g_mask[idx]);
    }
    #pragma unroll
    for (int o = 16; o; o >>= 1) s += __shfl_down_sync(~0u, s, o);
    if ((threadIdx.x & 31) == 0) shw[threadIdx.x >> 5] = s;
    __syncthreads();
    if (threadIdx.x == 0) {
        int t = 0;
        for (int k = 0; k < 8; k++) t += shw[k];
        g_bsums[blockIdx.x] = t;
    }
}

__global__ void k_scan_bsums(int nb) {
    __shared__ int sh[32];
    int t = threadIdx.x, lane = t & 31, w = t >> 5;
    int c = (nb + 1023) / 1024;
    int loc[16];
    int s = 0;
    for (int j = 0; j < c; j++) {
        int idx = t * c + j;
        int v = (idx < nb) ? g_bsums[idx] : 0;
        loc[j] = s; s += v;
    }
    int x = s;
    #pragma unroll
    for (int o = 1; o < 32; o <<= 1) { int y = __shfl_up_sync(~0u, x, o); if (lane >= o) x += y; }
    if (lane == 31) sh[w] = x;
    __syncthreads();
    if (t < 32) {
        int v2 = sh[t];
        #pragma unroll
        for (int o = 1; o < 32; o <<= 1) { int y = __shfl_up_sync(~0u, v2, o); if (t >= o) v2 += y; }
        sh[t] = v2;
    }
    __syncthreads();
    int excl = (w ? sh[w - 1] : 0) + x - s;
    for (int j = 0; j < c; j++) {
        int idx = t * c + j;
        if (idx < nb) g_bsums[idx] = excl + loc[j];
    }
}

// coalesced per-word rank prefix (SoA: read mask, write pfx)
__global__ void k_bits_final() {
    __shared__ int shw[8];
    int start = blockIdx.x * WPB;
    int base = g_bsums[blockIdx.x];
    for (int it = 0; it < WPB / 256; it++) {
        int idx = start + it * 256 + threadIdx.x;
        int pc = (idx < NWRD) ? __popc(g_mask[idx]) : 0;
        int tot;
        int excl = blockScanExcl256(pc, shw, tot);
        if (idx < NWRD) g_pfx[idx] = base + excl;
        base += tot;
    }
}

// thread per point: rank via popc, voxel_index output, count, cellof
__global__ void k_count(float* __restrict__ out, long long V, int n) {
    int i = blockIdx.x * blockDim.x + threadIdx.x;
    if (i >= n) return;
    int key = g_merge[i];
    int r = g_pfx[key >> 5] + __popc(g_mask[key >> 5] & ((1u << (key & 31)) - 1u));
    __stcs(&g_cellof[r], key);         // same-value race: benign
    out[52LL * V + i] = (float)r;
    atomicAdd(&g_vcount[r], 1);
}

__global__ void k_vcount_partial(int nV) {
    __shared__ int shw[8];
    int base = blockIdx.x * CPB;
    int s = 0;
    for (int it = 0; it < CPB / 256; it++) {
        int idx = base + it * 256 + threadIdx.x;
        if (idx < nV) s += g_vcount[idx];
    }
    #pragma unroll
    for (int o = 16; o; o >>= 1) s += __shfl_down_sync(~0u, s, o);
    if ((threadIdx.x & 31) == 0) shw[threadIdx.x >> 5] = s;
    __syncthreads();
    if (threadIdx.x == 0) {
        int t = 0;
        for (int k = 0; k < 8; k++) t += shw[k];
        g_bsums[blockIdx.x] = t;
    }
}

// voffset scan + fused multi-voxel accumulator zeroing + multi list
__global__ void k_vcount_final(float* __restrict__ out, long long V, int nV) {
    __shared__ int shw[8];
    int start = blockIdx.x * CPB;
    int base = g_bsums[blockIdx.x];
    for (int it = 0; it < CPB / 256; it++) {
        int idx = start + it * 256 + threadIdx.x;
        int v = (idx < nV) ? g_vcount[idx] : 0;
        int tot;
        int excl = blockScanExcl256(v, shw, tot);
        if (idx < nV) {
            g_voffset[idx] = base + excl;
            if (v > 1) {
                long long r = idx;
                out[15LL * V + r * 4 + 0] = 0.f;
                out[15LL * V + r * 4 + 1] = 0.f;
                out[15LL * V + r * 4 + 2] = 0.f;
                out[15LL * V + r * 4 + 3] = 0.f;
                float* fp = &out[19LL * V + r * 32];
                #pragma unroll
                for (int k = 0; k < 32; k++) fp[k] = 0.f;
                g_cursor[idx] = 0;
                g_multilist[atomicAdd(&g_nmulti, 1)] = idx;
            }
        }
        base += tot;
    }
}

// warp = 4 points; 8 lanes x float4 per point. VEC=4 requires V%4==0.
template <int VEC>
__global__ void k_accum2v(const float4* __restrict__ bxyz, const float4* __restrict__ feat4,
                          const float* __restrict__ h, float* __restrict__ out,
                          long long V, int n) {
    int gw = (blockIdx.x * blockDim.x + threadIdx.x) >> 5;
    int lane = threadIdx.x & 31;
    int sub = lane >> 3, comp = lane & 7;
    int i = gw * 4 + sub;
    if (i >= n) return;
    int key = g_merge[i];
    int r = g_pfx[key >> 5] + __popc(g_mask[key >> 5] & ((1u << (key & 31)) - 1u));
    int c = g_vcount[r];
    float4 f = __ldcs(&feat4[(long long)i * 8 + comp]);
    long long fbase = 19LL * V + (long long)r * 32 + comp * 4;
    if (c == 1) {
        if (VEC == 4) {
            __stcs((float4*)&out[fbase], f);
        } else {
            __stcs(&out[fbase + 0], f.x);
            __stcs(&out[fbase + 1], f.y);
            __stcs(&out[fbase + 2], f.z);
            __stcs(&out[fbase + 3], f.w);
        }
    } else {
        atomicAdd(&out[fbase + 0], f.x);
        atomicAdd(&out[fbase + 1], f.y);
        atomicAdd(&out[fbase + 2], f.z);
        atomicAdd(&out[fbase + 3], f.w);
    }
    if (comp == 0) {
        float4 b = __ldg(&bxyz[i]);
        long long bo = 15LL * V + (long long)r * 4;
        if (c == 1) {
            if (VEC == 4) {
                *(float4*)&out[bo] = b;
            } else {
                out[bo + 0] = b.x; out[bo + 1] = b.y;
                out[bo + 2] = b.z; out[bo + 3] = b.w;
            }
        } else {
            atomicAdd(&out[bo + 0], b.x);
            atomicAdd(&out[bo + 1], b.y);
            atomicAdd(&out[bo + 2], b.z);
            atomicAdd(&out[bo + 3], b.w);
        }
    } else if (comp == 1) {
        float tv = __fadd_rn(__fsub_rn(__ldg(&h[i]), g_st.hmin), __fmul_rn((float)r, g_st.hmax));
        int pos = (c == 1) ? 0 : atomicAdd(&g_cursor[r], 1);
        g_keyA[g_voffset[r] + pos] = fenc(tv);
    }
}

// warp = 4 multi-voxels; 8 lanes x float4 RW
template <int VEC>
__global__ void k_voxfin_feat(float* __restrict__ out, long long V) {
    int lane = threadIdx.x & 31;
    int gw = (blockIdx.x * blockDim.x + threadIdx.x) >> 5;
    int nw = (gridDim.x * blockDim.x) >> 5;
    int sub = lane >> 3, comp = lane & 7;
    int nm = g_nmulti;
    for (int j4 = gw * 4 + sub; j4 < nm; j4 += nw * 4) {
        long long r = g_multilist[j4];
        float fc = (float)g_vcount[r];
        long long o = 19LL * V + r * 32 + comp * 4;
        if (VEC == 4) {
            float4 v = *(float4*)&out[o];
            v.x = __fdiv_rn(v.x, fc);
            v.y = __fdiv_rn(v.y, fc);
            v.z = __fdiv_rn(v.z, fc);
            v.w = __fdiv_rn(v.w, fc);
            *(float4*)&out[o] = v;
        } else {
            #pragma unroll
            for (int k = 0; k < 4; k++) out[o + k] = __fdiv_rn(out[o + k], fc);
        }
    }
}

// fused: per-voxel scalar outputs + windowed-global-sort median (fast selection)
__global__ void k_final(float* __restrict__ out, const float* __restrict__ vs,
                        long long V, int N) {
    long long r = (long long)blockIdx.x * blockDim.x + threadIdx.x;
    if (r >= V) return;
    float vs1 = __ldg(&vs[1]), vs2 = __ldg(&vs[2]), vs3 = __ldg(&vs[3]);
    float mn1 = __uint_as_float(g_st.pcmin_bits[1]);
    float mn2 = __uint_as_float(g_st.pcmin_bits[2]);
    float mn3 = __uint_as_float(g_st.pcmin_bits[3]);
    int c = g_vcount[r];
    float sx = out[15LL * V + r * 4 + 0];
    float sy = out[15LL * V + r * 4 + 1];
    float sz = out[15LL * V + r * 4 + 2];
    float sw = out[15LL * V + r * 4 + 3];
    if (c > 1) {
        float fc = (float)c;
        sx = __fdiv_rn(sx, fc);
        sy = __fdiv_rn(sy, fc);
        sz = __fdiv_rn(sz, fc);
        sw = __fdiv_rn(sw, fc);
        out[15LL * V + r * 4 + 0] = sx;
        out[15LL * V + r * 4 + 1] = sy;
        out[15LL * V + r * 4 + 2] = sz;
        out[15LL * V + r * 4 + 3] = sw;
    }
    int key = g_cellof[r];
    int c0 = (key >> 24) & 255, c1 = (key >> 16) & 255, c2 = (key >> 8) & 255, c3 = key & 255;
    out[r] = (float)(int)rintf(sx);
    out[V + r * 3 + 0] = sy;
    out[V + r * 3 + 1] = sz;
    out[V + r * 3 + 2] = sw;
    float t1 = __fadd_rn(__fmul_rn((float)c1, vs1), mn1);
    float t2 = __fadd_rn(__fmul_rn((float)c2, vs2), mn2);
    float t3 = __fadd_rn(__fmul_rn((float)c3, vs3), mn3);
    float ctr1 = __fadd_rn(t1, __fdiv_rn(vs1, 2.0f));
    float ctr2 = __fadd_rn(t2, __fdiv_rn(vs2, 2.0f));
    float ctr3 = __fadd_rn(t3, __fdiv_rn(vs3, 2.0f));
    out[4LL * V + r * 3 + 0] = ctr1;
    out[4LL * V + r * 3 + 1] = ctr2;
    out[4LL * V + r * 3 + 2] = ctr3;
    out[7LL * V + r * 4 + 0] = sx;
    out[7LL * V + r * 4 + 1] = ctr1;
    out[7LL * V + r * 4 + 2] = ctr2;
    out[7LL * V + r * 4 + 3] = ctr3;
    out[11LL * V + r * 4 + 0] = (float)c0;
    out[11LL * V + r * 4 + 1] = (float)c1;
    out[11LL * V + r * 4 + 2] = (float)c2;
    out[11LL * V + r * 4 + 3] = (float)c3;

    // median: value at global-sort position voffset[r] + c/2, via windowed
    // selection with iterative min-with-multiplicity (exact vs full sort).
    float mx = g_st.hmax;
    int W = g_st.wwin;
    long long lo = r - W; if (lo < 0) lo = 0;
    long long hi = r + W; if (hi > V - 1) hi = V - 1;
    int s0 = g_voffset[lo];
    int sr = g_voffset[r];
    int s1 = (hi + 1 < V) ? g_voffset[hi + 1] : N;
    unsigned thr = fenc(__fmul_rn((float)r, mx));   // >= 0x80000000, so thr-1 safe
    int kk = c >> 1;
    for (int j = s0; j < sr; j++)
        if (__ldg(&g_keyA[j]) >= thr) kk++;
    unsigned last = thr - 1u;
    int remaining = kk + 1;
    unsigned ans = 0u;
    for (int guard = s1 - s0; guard > 0; guard--) {
        unsigned m = 0xFFFFFFFFu;
        int mult = 0;
        for (int j = s0; j < s1; j++) {
            unsigned k = __ldg(&g_keyA[j]);
            if (k > last) {
                if (k < m) { m = k; mult = 1; }
                else if (k == m) mult++;
            }
        }
        if (mult >= remaining) { ans = m; break; }
        remaining -= mult;
        last = m;
    }
    out[51LL * V + r] = __fsub_rn(fdec(ans), __fmul_rn((float)r, mx));
}

extern "C" void kernel_launch(void* const* d_in, const int* in_sizes, int n_in,
                              void* d_out, int out_size) {
    const float* bxyz = (const float*)d_in[0];
    const float* feat = (const float*)d_in[1];
    const float* hh = (const float*)d_in[2];
    const float* vs = (const float*)d_in[3];
    int N = in_sizes[0] / 4;
    long long V = ((long long)out_size - 5LL * N) / 52LL;
    float* out = (float*)d_out;

    void *p_mask = 0, *p_vcount = 0;
    cudaGetSymbolAddress(&p_mask, g_mask);
    cudaGetSymbolAddress(&p_vcount, g_vcount);

    int NBW = (NWRD + WPB - 1) / WPB;
    int NBV = (int)((V + CPB - 1) / CPB);
    int BPT = (N + 255) / 256;
    int BS4 = ((N + 3) / 4 + 255) / 256;
    long long warps4 = ((long long)N + 3) / 4;
    int BW4 = (int)((warps4 * 32 + 255) / 256);
    int BVT = (int)((V + 255) / 256);

    cudaMemsetAsync(p_mask, 0, sizeof(unsigned) * NWRD);
    cudaMemsetAsync(p_vcount, 0, sizeof(int) * (size_t)V);

    k_init<<<1, 32>>>();
    k_stats<<<BS4, 256>>>((const float4*)bxyz, (const float4*)hh, hh, N);
    k_merge<<<BPT, 256>>>((const float4*)bxyz, vs, out, V, N);
    k_bits_partial<<<NBW, 256>>>();
    k_scan_bsums<<<1, 1024>>>(NBW);
    k_bits_final<<<NBW, 256>>>();
    k_count<<<BPT, 256>>>(out, V, N);
    k_vcount_partial<<<NBV, 256>>>((int)V);
    k_scan_bsums<<<1, 1024>>>(NBV);
    k_vcount_final<<<NBV, 256>>>(out, V, (int)V);
    if ((V & 3) == 0) {
        k_accum2v<4><<<BW4, 256>>>((const float4*)bxyz, (const float4*)feat, hh, out, V, N);
        k_voxfin_feat<4><<<2048, 256>>>(out, V);
    } else {
        k_accum2v<1><<<BW4, 256>>>((const float4*)bxyz, (const float4*)feat, hh, out, V, N);
        k_voxfin_feat<1><<<2048, 256>>>(out, V);
    }
    k_final<<<BVT, 256>>>(out, vs, V, N);
}

// round 15
// speedup vs baseline: 1.0325x; 1.0089x over previous
#include <cuda_runtime.h>

#define NMAX 2000128
#define NKEY (1 << 26)
#define NWRD (NKEY / 32)
#define WPB 8192
#define CPB 8192

__device__ unsigned g_mask[NWRD];       // occupancy bitmask (memset 0)
__device__ int g_pfx[NWRD];             // exclusive rank prefix per word
__device__ int g_merge[NMAX];           // bitfield key per point
__device__ unsigned g_keyA[NMAX];       // encoded tvals binned by voxel
__device__ int g_vcount[NMAX];          // zeroed by k_final at end of each run
__device__ int g_voffset[NMAX];
__device__ int g_cellof[NMAX];          // rank -> bitfield key (written rank-sequential)
__device__ int g_cursor[NMAX];
__device__ int g_bsums[8448];
__device__ int g_multilist[NMAX];
__device__ int g_nmulti;

struct Stats {
    unsigned pcmin_bits[4];
    unsigned hmin_e, hmax_e;
    float hmin, hmax;
    int wwin;
};
__device__ Stats g_st;

__device__ __forceinline__ unsigned fenc(float f) {
    unsigned b = __float_as_uint(f);
    return (b & 0x80000000u) ? ~b : (b | 0x80000000u);
}
__device__ __forceinline__ float fdec(unsigned u) {
    return __uint_as_float((u & 0x80000000u) ? (u ^ 0x80000000u) : ~u);
}

__global__ void k_init() {
    int t = threadIdx.x;
    if (t < 4) g_st.pcmin_bits[t] = 0x7F800000u;
    if (t == 4) { g_st.hmin_e = 0xFFFFFFFFu; g_st.hmax_e = 0u; g_nmulti = 0; }
}

__global__ void k_stats(const float4* __restrict__ bxyz, const float4* __restrict__ h4,
                        const float* __restrict__ h, int n) {
    int t = blockIdx.x * blockDim.x + threadIdx.x;
    int base = t * 4;
    float m0 = 3.4e38f, m1 = 3.4e38f, m2 = 3.4e38f, m3 = 3.4e38f;
    unsigned he0 = 0xFFFFFFFFu, he1 = 0u;
    if (base + 3 < n) {
        float4 p0 = __ldg(&bxyz[base]);
        float4 p1 = __ldg(&bxyz[base + 1]);
        float4 p2 = __ldg(&bxyz[base + 2]);
        float4 p3 = __ldg(&bxyz[base + 3]);
        float4 hv = __ldg(&h4[t]);
        m0 = fminf(fminf(p0.x, p1.x), fminf(p2.x, p3.x));
        m1 = fminf(fminf(p0.y, p1.y), fminf(p2.y, p3.y));
        m2 = fminf(fminf(p0.z, p1.z), fminf(p2.z, p3.z));
        m3 = fminf(fminf(p0.w, p1.w), fminf(p2.w, p3.w));
        unsigned e0 = fenc(hv.x), e1 = fenc(hv.y), e2 = fenc(hv.z), e3 = fenc(hv.w);
        he0 = min(min(e0, e1), min(e2, e3));
        he1 = max(max(e0, e1), max(e2, e3));
    } else {
        for (int i = base; i < n; i++) {
            float4 p = __ldg(&bxyz[i]);
            m0 = fminf(m0, p.x); m1 = fminf(m1, p.y);
            m2 = fminf(m2, p.z); m3 = fminf(m3, p.w);
            unsigned e = fenc(__ldg(&h[i]));
            he0 = min(he0, e); he1 = max(he1, e);
        }
    }
    #pragma unroll
    for (int o = 16; o; o >>= 1) {
        m0 = fminf(m0, __shfl_down_sync(~0u, m0, o));
        m1 = fminf(m1, __shfl_down_sync(~0u, m1, o));
        m2 = fminf(m2, __shfl_down_sync(~0u, m2, o));
        m3 = fminf(m3, __shfl_down_sync(~0u, m3, o));
        he0 = min(he0, __shfl_down_sync(~0u, he0, o));
        he1 = max(he1, __shfl_down_sync(~0u, he1, o));
    }
    if ((threadIdx.x & 31) == 0) {
        atomicMin(&g_st.pcmin_bits[0], __float_as_uint(m0));
        atomicMin(&g_st.pcmin_bits[1], __float_as_uint(m1));
        atomicMin(&g_st.pcmin_bits[2], __float_as_uint(m2));
        atomicMin(&g_st.pcmin_bits[3], __float_as_uint(m3));
        atomicMin(&g_st.hmin_e, he0);
        atomicMax(&g_st.hmax_e, he1);
    }
}

__global__ void k_merge(const float4* __restrict__ bxyz, const float* __restrict__ vs,
                        float* __restrict__ out, long long V, int n) {
    float mn0 = __uint_as_float(g_st.pcmin_bits[0]);
    float mn1 = __uint_as_float(g_st.pcmin_bits[1]);
    float mn2 = __uint_as_float(g_st.pcmin_bits[2]);
    float mn3 = __uint_as_float(g_st.pcmin_bits[3]);
    float v0 = __ldg(&vs[0]), v1 = __ldg(&vs[1]), v2 = __ldg(&vs[2]), v3 = __ldg(&vs[3]);
    long long O9 = 52LL * V + n;
    int i = blockIdx.x * blockDim.x + threadIdx.x;
    if (i >= n) return;
    float4 p = __ldg(&bxyz[i]);
    int c0 = (int)floorf(__fdiv_rn(__fsub_rn(p.x, mn0), v0));
    int c1 = (int)floorf(__fdiv_rn(__fsub_rn(p.y, mn1), v1));
    int c2 = (int)floorf(__fdiv_rn(__fsub_rn(p.z, mn2), v2));
    int c3 = (int)floorf(__fdiv_rn(__fsub_rn(p.w, mn3), v3));
    int key = (c0 << 24) | (c1 << 16) | (c2 << 8) | c3;
    g_merge[i] = key;
    atomicOr(&g_mask[key >> 5], 1u << (key & 31));
    *(float4*)&out[O9 + 4LL * i] = make_float4((float)c0, (float)c1, (float)c2, (float)c3);
}

__device__ __forceinline__ int blockScanExcl256(int v, int* shw, int& total) {
    int lane = threadIdx.x & 31, w = threadIdx.x >> 5;
    int x = v;
    #pragma unroll
    for (int o = 1; o < 32; o <<= 1) { int y = __shfl_up_sync(~0u, x, o); if (lane >= o) x += y; }
    if (lane == 31) shw[w] = x;
    __syncthreads();
    if (threadIdx.x < 8) {
        int s = shw[threadIdx.x];
        #pragma unroll
        for (int o = 1; o < 8; o <<= 1) { int y = __shfl_up_sync(0xFFu, s, o); if ((int)threadIdx.x >= o) s += y; }
        shw[threadIdx.x] = s;
    }
    __syncthreads();
    int excl = (w ? shw[w - 1] : 0) + x - v;
    total = shw[7];
    __syncthreads();
    return excl;
}

// per-tile popcount sums; block 0 thread 0 finalizes stats
__global__ void k_bits_partial() {
    __shared__ int shw[8];
    if (blockIdx.x == 0 && threadIdx.x == 0) {
        float mn = fdec(g_st.hmin_e), mx = fdec(g_st.hmax_e);
        g_st.hmin = mn; g_st.hmax = mx;
        int w = 64;
        if (mx > 0.0f) {
            float ratio = (mx - mn) / mx;
            if (ratio < 60.0f) w = (int)ratio + 2;
        }
        g_st.wwin = w;
    }
    int base = blockIdx.x * WPB;
    int s = 0;
    for (int it = 0; it < WPB / 256; it++) {
        int idx = base + it * 256 + threadIdx.x;
        if (idx < NWRD) s += __popc(g_mask[idx]);
    }
    #pragma unroll
    for (int o = 16; o; o >>= 1) s += __shfl_down_sync(~0u, s, o);
    if ((threadIdx.x & 31) == 0) shw[threadIdx.x >> 5] = s;
    __syncthreads();
    if (threadIdx.x == 0) {
        int t = 0;
        for (int k = 0; k < 8; k++) t += shw[k];
        g_bsums[blockIdx.x] = t;
    }
}

__global__ void k_scan_bsums(int nb) {
    __shared__ int sh[32];
    int t = threadIdx.x, lane = t & 31, w = t >> 5;
    int c = (nb + 1023) / 1024;
    int loc[16];
    int s = 0;
    for (int j = 0; j < c; j++) {
        int idx = t * c + j;
        int v = (idx < nb) ? g_bsums[idx] : 0;
        loc[j] = s; s += v;
    }
    int x = s;
    #pragma unroll
    for (int o = 1; o < 32; o <<= 1) { int y = __shfl_up_sync(~0u, x, o); if (lane >= o) x += y; }
    if (lane == 31) sh[w] = x;
    __syncthreads();
    if (t < 32) {
        int v2 = sh[t];
        #pragma unroll
        for (int o = 1; o < 32; o <<= 1) { int y = __shfl_up_sync(~0u, v2, o); if (t >= o) v2 += y; }
        sh[t] = v2;
    }
    __syncthreads();
    int excl = (w ? sh[w - 1] : 0) + x - s;
    for (int j = 0; j < c; j++) {
        int idx = t * c + j;
        if (idx < nb) g_bsums[idx] = excl + loc[j];
    }
}

// per-word rank prefix + rank-sequential cellof writes (coalesced in r)
__global__ void k_bits_final() {
    __shared__ int shw[8];
    int start = blockIdx.x * WPB;
    int base = g_bsums[blockIdx.x];
    for (int it = 0; it < WPB / 256; it++) {
        int idx = start + it * 256 + threadIdx.x;
        unsigned w = (idx < NWRD) ? g_mask[idx] : 0u;
        int pc = __popc(w);
        int tot;
        int excl = blockScanExcl256(pc, shw, tot);
        if (idx < NWRD) {
            g_pfx[idx] = base + excl;
            int r = base + excl;
            while (w) {
                int j = __ffs(w) - 1;
                w &= w - 1;
                g_cellof[r] = idx * 32 + j;
                r++;
            }
        }
        base += tot;
    }
}

// thread per point: rank via popc, voxel_index output, count
__global__ void k_count(float* __restrict__ out, long long V, int n) {
    int i = blockIdx.x * blockDim.x + threadIdx.x;
    if (i >= n) return;
    int key = g_merge[i];
    int r = g_pfx[key >> 5] + __popc(g_mask[key >> 5] & ((1u << (key & 31)) - 1u));
    out[52LL * V + i] = (float)r;
    atomicAdd(&g_vcount[r], 1);
}

__global__ void k_vcount_partial(int nV) {
    __shared__ int shw[8];
    int base = blockIdx.x * CPB;
    int s = 0;
    for (int it = 0; it < CPB / 256; it++) {
        int idx = base + it * 256 + threadIdx.x;
        if (idx < nV) s += g_vcount[idx];
    }
    #pragma unroll
    for (int o = 16; o; o >>= 1) s += __shfl_down_sync(~0u, s, o);
    if ((threadIdx.x & 31) == 0) shw[threadIdx.x >> 5] = s;
    __syncthreads();
    if (threadIdx.x == 0) {
        int t = 0;
        for (int k = 0; k < 8; k++) t += shw[k];
        g_bsums[blockIdx.x] = t;
    }
}

// voffset scan + fused multi-voxel accumulator zeroing + multi list
__global__ void k_vcount_final(float* __restrict__ out, long long V, int nV) {
    __shared__ int shw[8];
    int start = blockIdx.x * CPB;
    int base = g_bsums[blockIdx.x];
    for (int it = 0; it < CPB / 256; it++) {
        int idx = start + it * 256 + threadIdx.x;
        int v = (idx < nV) ? g_vcount[idx] : 0;
        int tot;
        int excl = blockScanExcl256(v, shw, tot);
        if (idx < nV) {
            g_voffset[idx] = base + excl;
            if (v > 1) {
                long long r = idx;
                out[15LL * V + r * 4 + 0] = 0.f;
                out[15LL * V + r * 4 + 1] = 0.f;
                out[15LL * V + r * 4 + 2] = 0.f;
                out[15LL * V + r * 4 + 3] = 0.f;
                float* fp = &out[19LL * V + r * 32];
                #pragma unroll
                for (int k = 0; k < 32; k++) fp[k] = 0.f;
                g_cursor[idx] = 0;
                g_multilist[atomicAdd(&g_nmulti, 1)] = idx;
            }
        }
        base += tot;
    }
}

// warp = 4 points; 8 lanes x float4 per point. VEC=4 requires V%4==0.
template <int VEC>
__global__ void k_accum2v(const float4* __restrict__ bxyz, const float4* __restrict__ feat4,
                          const float* __restrict__ h, float* __restrict__ out,
                          long long V, int n) {
    int gw = (blockIdx.x * blockDim.x + threadIdx.x) >> 5;
    int lane = threadIdx.x & 31;
    int sub = lane >> 3, comp = lane & 7;
    int i = gw * 4 + sub;
    if (i >= n) return;
    int key = g_merge[i];
    int r = g_pfx[key >> 5] + __popc(g_mask[key >> 5] & ((1u << (key & 31)) - 1u));
    int c = g_vcount[r];
    float4 f = __ldcs(&feat4[(long long)i * 8 + comp]);
    long long fbase = 19LL * V + (long long)r * 32 + comp * 4;
    if (c == 1) {
        if (VEC == 4) {
            __stcs((float4*)&out[fbase], f);
        } else {
            __stcs(&out[fbase + 0], f.x);
            __stcs(&out[fbase + 1], f.y);
            __stcs(&out[fbase + 2], f.z);
            __stcs(&out[fbase + 3], f.w);
        }
    } else {
        atomicAdd(&out[fbase + 0], f.x);
        atomicAdd(&out[fbase + 1], f.y);
        atomicAdd(&out[fbase + 2], f.z);
        atomicAdd(&out[fbase + 3], f.w);
    }
    if (comp == 0) {
        float4 b = __ldg(&bxyz[i]);
        long long bo = 15LL * V + (long long)r * 4;
        if (c == 1) {
            if (VEC == 4) {
                *(float4*)&out[bo] = b;
            } else {
                out[bo + 0] = b.x; out[bo + 1] = b.y;
                out[bo + 2] = b.z; out[bo + 3] = b.w;
            }
        } else {
            atomicAdd(&out[bo + 0], b.x);
            atomicAdd(&out[bo + 1], b.y);
            atomicAdd(&out[bo + 2], b.z);
            atomicAdd(&out[bo + 3], b.w);
        }
    } else if (comp == 1) {
        float tv = __fadd_rn(__fsub_rn(__ldg(&h[i]), g_st.hmin), __fmul_rn((float)r, g_st.hmax));
        int pos = (c == 1) ? 0 : atomicAdd(&g_cursor[r], 1);
        g_keyA[g_voffset[r] + pos] = fenc(tv);
    }
}

// warp = 4 multi-voxels; 8 lanes x float4 RW
template <int VEC>
__global__ void k_voxfin_feat(float* __restrict__ out, long long V) {
    int lane = threadIdx.x & 31;
    int gw = (blockIdx.x * blockDim.x + threadIdx.x) >> 5;
    int nw = (gridDim.x * blockDim.x) >> 5;
    int sub = lane >> 3, comp = lane & 7;
    int nm = g_nmulti;
    for (int j4 = gw * 4 + sub; j4 < nm; j4 += nw * 4) {
        long long r = g_multilist[j4];
        float fc = (float)g_vcount[r];
        long long o = 19LL * V + r * 32 + comp * 4;
        if (VEC == 4) {
            float4 v = *(float4*)&out[o];
            v.x = __fdiv_rn(v.x, fc);
            v.y = __fdiv_rn(v.y, fc);
            v.z = __fdiv_rn(v.z, fc);
            v.w = __fdiv_rn(v.w, fc);
            *(float4*)&out[o] = v;
        } else {
            #pragma unroll
            for (int k = 0; k < 4; k++) out[o + k] = __fdiv_rn(out[o + k], fc);
        }
    }
}

// fused: per-voxel scalar outputs + windowed-global-sort median (fast selection).
// Zeroes g_vcount[r] at the end so the next graph replay starts clean (replaces
// the vcount memset node; deterministic across replays).
__global__ void k_final(float* __restrict__ out, const float* __restrict__ vs,
                        long long V, int N) {
    long long r = (long long)blockIdx.x * blockDim.x + threadIdx.x;
    if (r >= V) return;
    float vs1 = __ldg(&vs[1]), vs2 = __ldg(&vs[2]), vs3 = __ldg(&vs[3]);
    float mn1 = __uint_as_float(g_st.pcmin_bits[1]);
    float mn2 = __uint_as_float(g_st.pcmin_bits[2]);
    float mn3 = __uint_as_float(g_st.pcmin_bits[3]);
    int c = g_vcount[r];
    float sx = out[15LL * V + r * 4 + 0];
    float sy = out[15LL * V + r * 4 + 1];
    float sz = out[15LL * V + r * 4 + 2];
    float sw = out[15LL * V + r * 4 + 3];
    if (c > 1) {
        float fc = (float)c;
        sx = __fdiv_rn(sx, fc);
        sy = __fdiv_rn(sy, fc);
        sz = __fdiv_rn(sz, fc);
        sw = __fdiv_rn(sw, fc);
        out[15LL * V + r * 4 + 0] = sx;
        out[15LL * V + r * 4 + 1] = sy;
        out[15LL * V + r * 4 + 2] = sz;
        out[15LL * V + r * 4 + 3] = sw;
    }
    int key = g_cellof[r];
    int c0 = (key >> 24) & 255, c1 = (key >> 16) & 255, c2 = (key >> 8) & 255, c3 = key & 255;
    out[r] = (float)(int)rintf(sx);
    out[V + r * 3 + 0] = sy;
    out[V + r * 3 + 1] = sz;
    out[V + r * 3 + 2] = sw;
    float t1 = __fadd_rn(__fmul_rn((float)c1, vs1), mn1);
    float t2 = __fadd_rn(__fmul_rn((float)c2, vs2), mn2);
    float t3 = __fadd_rn(__fmul_rn((float)c3, vs3), mn3);
    float ctr1 = __fadd_rn(t1, __fdiv_rn(vs1, 2.0f));
    float ctr2 = __fadd_rn(t2, __fdiv_rn(vs2, 2.0f));
    float ctr3 = __fadd_rn(t3, __fdiv_rn(vs3, 2.0f));
    out[4LL * V + r * 3 + 0] = ctr1;
    out[4LL * V + r * 3 + 1] = ctr2;
    out[4LL * V + r * 3 + 2] = ctr3;
    out[7LL * V + r * 4 + 0] = sx;
    out[7LL * V + r * 4 + 1] = ctr1;
    out[7LL * V + r * 4 + 2] = ctr2;
    out[7LL * V + r * 4 + 3] = ctr3;
    out[11LL * V + r * 4 + 0] = (float)c0;
    out[11LL * V + r * 4 + 1] = (float)c1;
    out[11LL * V + r * 4 + 2] = (float)c2;
    out[11LL * V + r * 4 + 3] = (float)c3;

    // median: value at global-sort position voffset[r] + c/2, via windowed
    // selection with iterative min-with-multiplicity (exact vs full sort).
    float mx = g_st.hmax;
    int W = g_st.wwin;
    long long lo = r - W; if (lo < 0) lo = 0;
    long long hi = r + W; if (hi > V - 1) hi = V - 1;
    int s0 = g_voffset[lo];
    int sr = g_voffset[r];
    int s1 = (hi + 1 < V) ? g_voffset[hi + 1] : N;
    unsigned thr = fenc(__fmul_rn((float)r, mx));   // >= 0x80000000, so thr-1 safe
    int kk = c >> 1;
    for (int j = s0; j < sr; j++)
        if (__ldg(&g_keyA[j]) >= thr) kk++;
    unsigned last = thr - 1u;
    int remaining = kk + 1;
    unsigned ans = 0u;
    for (int guard = s1 - s0; guard > 0; guard--) {
        unsigned m = 0xFFFFFFFFu;
        int mult = 0;
        for (int j = s0; j < s1; j++) {
            unsigned k = __ldg(&g_keyA[j]);
            if (k > last) {
                if (k < m) { m = k; mult = 1; }
                else if (k == m) mult++;
            }
        }
        if (mult >= remaining) { ans = m; break; }
        remaining -= mult;
        last = m;
    }
    out[51LL * V + r] = __fsub_rn(fdec(ans), __fmul_rn((float)r, mx));

    g_vcount[r] = 0;   // clean for next replay (replaces memset node)
}

extern "C" void kernel_launch(void* const* d_in, const int* in_sizes, int n_in,
                              void* d_out, int out_size) {
    const float* bxyz = (const float*)d_in[0];
    const float* feat = (const float*)d_in[1];
    const float* hh = (const float*)d_in[2];
    const float* vs = (const float*)d_in[3];
    int N = in_sizes[0] / 4;
    long long V = ((long long)out_size - 5LL * N) / 52LL;
    float* out = (float*)d_out;

    void* p_mask = 0;
    cudaGetSymbolAddress(&p_mask, g_mask);

    int NBW = (NWRD + WPB - 1) / WPB;
    int NBV = (int)((V + CPB - 1) / CPB);
    int BPT = (N + 255) / 256;
    int BS4 = ((N + 3) / 4 + 255) / 256;
    long long warps4 = ((long long)N + 3) / 4;
    int BW4 = (int)((warps4 * 32 + 255) / 256);
    int BVT = (int)((V + 255) / 256);

    cudaMemsetAsync(p_mask, 0, sizeof(unsigned) * NWRD);

    k_init<<<1, 32>>>();
    k_stats<<<BS4, 256>>>((const float4*)bxyz, (const float4*)hh, hh, N);
    k_merge<<<BPT, 256>>>((const float4*)bxyz, vs, out, V, N);
    k_bits_partial<<<NBW, 256>>>();
    k_scan_bsums<<<1, 1024>>>(NBW);
    k_bits_final<<<NBW, 256>>>();
    k_count<<<BPT, 256>>>(out, V, N);
    k_vcount_partial<<<NBV, 256>>>((int)V);
    k_scan_bsums<<<1, 1024>>>(NBV);
    k_vcount_final<<<NBV, 256>>>(out, V, (int)V);
    if ((V & 3) == 0) {
        k_accum2v<4><<<BW4, 256>>>((const float4*)bxyz, (const float4*)feat, hh, out, V, N);
        k_voxfin_feat<4><<<2048, 256>>>(out, V);
    } else {
        k_accum2v<1><<<BW4, 256>>>((const float4*)bxyz, (const float4*)feat, hh, out, V, N);
        k_voxfin_feat<1><<<2048, 256>>>(out, V);
    }
    k_final<<<BVT, 256>>>(out, vs, V, N);
}